// round 6
// baseline (speedup 1.0000x reference)
#include <cuda_runtime.h>
#include <cstdint>

// MeanAggregator: out[b, :] = (1/S) * sum_{s<S} features[neigh_idx[b,s], :]
// B=50000, S=10, N=1e6, D=128 (fp32), neigh_idx int32.
// R6: TWO nodes per warp with interleaved gather chains — forces ptxas to
// keep two independent load->accumulate chains live (~2x per-warp MLP vs the
// single-chain schedule it insists on at regs=32). Streaming stores (__stcs)
// for the write-once output.

#define D_DIM 128

template<int S>
__global__ __launch_bounds__(256)
void mean_agg_kernel2(const int* __restrict__ neigh_idx,
                      const float* __restrict__ features,
                      float* __restrict__ out,
                      int B, float inv_s)
{
    // Each warp owns nodes {2*warp, 2*warp+1}.
    int warp = (blockIdx.x * blockDim.x + threadIdx.x) >> 5;
    int lane = threadIdx.x & 31;
    int n0 = 2 * warp;
    int n1 = 2 * warp + 1;
    if (n0 >= B) return;
    bool has1 = (n1 < B);

    const int* __restrict__ ia = neigh_idx + (long long)n0 * S;
    const int* __restrict__ ib = neigh_idx + (long long)n1 * S;

    int ra[S], rb[S];
#pragma unroll
    for (int s = 0; s < S; s++) {
        ra[s] = __ldg(ia + s);
        rb[s] = has1 ? __ldg(ib + s) : ra[s];
    }

    float4 acc0 = make_float4(0.f, 0.f, 0.f, 0.f);
    float4 acc1 = make_float4(0.f, 0.f, 0.f, 0.f);

    // Interleave the two chains: loads for both nodes issued together each
    // step, accumulated into separate accumulators — two independent
    // dependency chains ptxas cannot merge.
#pragma unroll
    for (int s = 0; s < S; s++) {
        float4 va = __ldg(reinterpret_cast<const float4*>(
            features + (long long)ra[s] * D_DIM) + lane);
        float4 vb = __ldg(reinterpret_cast<const float4*>(
            features + (long long)rb[s] * D_DIM) + lane);
        acc0.x += va.x; acc0.y += va.y; acc0.z += va.z; acc0.w += va.w;
        acc1.x += vb.x; acc1.y += vb.y; acc1.z += vb.z; acc1.w += vb.w;
    }

    acc0.x *= inv_s; acc0.y *= inv_s; acc0.z *= inv_s; acc0.w *= inv_s;
    acc1.x *= inv_s; acc1.y *= inv_s; acc1.z *= inv_s; acc1.w *= inv_s;

    __stcs(reinterpret_cast<float4*>(out + (long long)n0 * D_DIM) + lane, acc0);
    if (has1)
        __stcs(reinterpret_cast<float4*>(out + (long long)n1 * D_DIM) + lane, acc1);
}

// Generic fallback (S not known at compile time).
__global__ __launch_bounds__(256)
void mean_agg_kernel_dyn(const int* __restrict__ neigh_idx,
                         const float* __restrict__ features,
                         float* __restrict__ out,
                         int B, int S, float inv_s)
{
    int warp = (blockIdx.x * blockDim.x + threadIdx.x) >> 5;
    int lane = threadIdx.x & 31;
    if (warp >= B) return;

    const int* __restrict__ idx_row = neigh_idx + (long long)warp * S;
    float4 acc = make_float4(0.f, 0.f, 0.f, 0.f);
    for (int s = 0; s < S; s++) {
        int r = idx_row[s];
        float4 vv = __ldg(reinterpret_cast<const float4*>(
            features + (long long)r * D_DIM) + lane);
        acc.x += vv.x; acc.y += vv.y; acc.z += vv.z; acc.w += vv.w;
    }
    acc.x *= inv_s; acc.y *= inv_s; acc.z *= inv_s; acc.w *= inv_s;
    reinterpret_cast<float4*>(out + (long long)warp * D_DIM)[lane] = acc;
}

extern "C" void kernel_launch(void* const* d_in, const int* in_sizes, int n_in,
                              void* d_out, int out_size)
{
    const int*   neigh_idx = (const int*)d_in[0];   // [B, S] int32
    const float* features  = (const float*)d_in[1]; // [N, D] fp32

    int B = out_size / D_DIM;
    int S = in_sizes[0] / B;
    float inv_s = 1.0f / (float)S;
    float* out = (float*)d_out;

    if (S == 10) {
        int node_pairs = (B + 1) / 2;              // warps needed
        int warps_per_block = 256 / 32;
        int grid = (node_pairs + warps_per_block - 1) / warps_per_block;
        mean_agg_kernel2<10><<<grid, 256>>>(neigh_idx, features, out, B, inv_s);
    } else {
        int warps_per_block = 256 / 32;
        int grid = (B + warps_per_block - 1) / warps_per_block;
        mean_agg_kernel_dyn<<<grid, 256>>>(neigh_idx, features, out, B, S, inv_s);
    }
}

// round 7
// speedup vs baseline: 1.0394x; 1.0394x over previous
#include <cuda_runtime.h>
#include <cstdint>

// MeanAggregator: out[b, :] = (1/S) * sum_{s<S} features[neigh_idx[b,s], :]
// B=50000, S=10, N=1e6, D=128 (fp32), neigh_idx int32.
// R7: cp.async (LDGSTS) gather — no destination registers, so all S row
// copies issue back-to-back (true MLP=S per warp) regardless of ptxas's
// regs=32 scheduling. Warp per node: each lane cp.asyncs 16B of each 512B
// row into smem, waits once, then accumulates from smem (conflict-free).

#define D_DIM 128
#define WARPS_PER_BLOCK 8
#define ROW_BYTES (D_DIM * 4)          // 512B
#define S_MAX 10

__device__ __forceinline__ unsigned smem_u32(const void* p) {
    return (unsigned)__cvta_generic_to_shared(p);
}

__device__ __forceinline__ void cp_async16(unsigned dst, const void* src) {
    asm volatile("cp.async.cg.shared.global [%0], [%1], 16;"
                 :: "r"(dst), "l"(src) : "memory");
}

template<int S>
__global__ __launch_bounds__(256)
void mean_agg_cpasync(const int* __restrict__ neigh_idx,
                      const float* __restrict__ features,
                      float* __restrict__ out,
                      int B, float inv_s)
{
    // [warp][s][512B] staging
    __shared__ __align__(16) float stage[WARPS_PER_BLOCK][S][D_DIM];

    int wib  = threadIdx.x >> 5;                         // warp in block
    int warp = blockIdx.x * WARPS_PER_BLOCK + wib;       // node id
    int lane = threadIdx.x & 31;
    if (warp >= B) return;

    const int* __restrict__ idx_row = neigh_idx + (long long)warp * S;

    int rows[S];
#pragma unroll
    for (int s = 0; s < S; s++) rows[s] = __ldg(idx_row + s);

    // Issue all S async copies back-to-back: 16B per lane per row.
#pragma unroll
    for (int s = 0; s < S; s++) {
        const float* src = features + (long long)rows[s] * D_DIM + lane * 4;
        unsigned dst = smem_u32(&stage[wib][s][lane * 4]);
        cp_async16(dst, src);
    }
    asm volatile("cp.async.commit_group;" ::: "memory");
    asm volatile("cp.async.wait_group 0;" ::: "memory");
    __syncwarp();

    // Accumulate from smem: lane reads its own 16B column of each row.
    float4 acc = make_float4(0.f, 0.f, 0.f, 0.f);
#pragma unroll
    for (int s = 0; s < S; s++) {
        float4 v = *reinterpret_cast<const float4*>(&stage[wib][s][lane * 4]);
        acc.x += v.x; acc.y += v.y; acc.z += v.z; acc.w += v.w;
    }
    acc.x *= inv_s; acc.y *= inv_s; acc.z *= inv_s; acc.w *= inv_s;

    reinterpret_cast<float4*>(out + (long long)warp * D_DIM)[lane] = acc;
}

// Generic fallback (S not known at compile time).
__global__ __launch_bounds__(256)
void mean_agg_kernel_dyn(const int* __restrict__ neigh_idx,
                         const float* __restrict__ features,
                         float* __restrict__ out,
                         int B, int S, float inv_s)
{
    int warp = (blockIdx.x * blockDim.x + threadIdx.x) >> 5;
    int lane = threadIdx.x & 31;
    if (warp >= B) return;

    const int* __restrict__ idx_row = neigh_idx + (long long)warp * S;
    float4 acc = make_float4(0.f, 0.f, 0.f, 0.f);
    for (int s = 0; s < S; s++) {
        int r = idx_row[s];
        float4 vv = __ldg(reinterpret_cast<const float4*>(
            features + (long long)r * D_DIM) + lane);
        acc.x += vv.x; acc.y += vv.y; acc.z += vv.z; acc.w += vv.w;
    }
    acc.x *= inv_s; acc.y *= inv_s; acc.z *= inv_s; acc.w *= inv_s;
    reinterpret_cast<float4*>(out + (long long)warp * D_DIM)[lane] = acc;
}

extern "C" void kernel_launch(void* const* d_in, const int* in_sizes, int n_in,
                              void* d_out, int out_size)
{
    const int*   neigh_idx = (const int*)d_in[0];   // [B, S] int32
    const float* features  = (const float*)d_in[1]; // [N, D] fp32

    int B = out_size / D_DIM;
    int S = in_sizes[0] / B;
    float inv_s = 1.0f / (float)S;
    float* out = (float*)d_out;

    if (S == 10) {
        int grid = (B + WARPS_PER_BLOCK - 1) / WARPS_PER_BLOCK;
        mean_agg_cpasync<10><<<grid, 256>>>(neigh_idx, features, out, B, inv_s);
    } else {
        int warps_per_block = 256 / 32;
        int grid = (B + warps_per_block - 1) / warps_per_block;
        mean_agg_kernel_dyn<<<grid, 256>>>(neigh_idx, features, out, B, S, inv_s);
    }
}